// round 11
// baseline (speedup 1.0000x reference)
#include <cuda_runtime.h>
#include <math.h>
#include <stdint.h>

// ---------------- problem constants ----------------
#define N_SRC   50000
#define N_DST   50000
#define E_NUM   800000
#define IN_NODE 128
#define OUT_NODE 64
#define NHEAD   4
#define HN      (NHEAD*OUT_NODE)   // 256
#define HE      64                 // NHEAD*OUT_EDGE
#define NCAT    (HN + HE)          // 320
#define SLOPE   0.01f
#define OUT_ELEMS (N_DST*OUT_NODE) // 3,200,000
// compensation for tf32-truncation of A (mean rel bias -2^-11*ln2)
#define CFAC    1.000338f

// ---------------- scratch (device globals; allocation-free) ----------------
__device__ __align__(16) float g_proj[(size_t)N_SRC * NCAT];   // 64 MB fp32
__device__ __align__(16) float g_fnj [(size_t)N_DST * HE];     // 12.8 MB
__device__ __align__(16) float g_a   [(size_t)E_NUM * NHEAD];  // edge order
__device__ __align__(16) float g_s   [(size_t)N_DST * NHEAD];
__device__ __align__(16) float g_is  [(size_t)N_DST * NHEAD];  // 0.25/s
__device__ __align__(16) float g_wcat[IN_NODE * NCAT];
__device__ __align__(16) float g_wnj [IN_NODE * HE];
__device__ __align__(16) float g_bcat[NCAT];
__device__ __align__(16) float g_wsum[HE];
// CSR by src
__device__ int g_cnt[N_SRC];
__device__ int g_rowp[N_SRC + 1];
__device__ int g_cur[N_SRC];
__device__ int g_eid[E_NUM];

// ---------------- helpers ----------------
__device__ __forceinline__ void redAddF4(float4* p, float4 v) {
    asm volatile("red.global.add.v4.f32 [%0], {%1, %2, %3, %4};"
                 :: "l"(__cvta_generic_to_global(p)),
                    "f"(v.x), "f"(v.y), "f"(v.z), "f"(v.w)
                 : "memory");
}
__device__ __forceinline__ void redAddF1(float* p, float v) {
    asm volatile("red.global.add.f32 [%0], %1;"
                 :: "l"(__cvta_generic_to_global(p)), "f"(v) : "memory");
}
__device__ __forceinline__ float leaky(float x) {
    return x >= 0.f ? x : SLOPE * x;
}
__device__ __forceinline__ uint32_t f2tf(float f) {
    uint32_t r;
    asm("cvt.rna.tf32.f32 %0, %1;" : "=r"(r) : "f"(f));
    return r;
}
__device__ __forceinline__ void mma_tf32(float* d, const uint32_t* a, const uint32_t* b) {
    asm volatile(
        "mma.sync.aligned.m16n8k8.row.col.f32.tf32.tf32.f32 "
        "{%0,%1,%2,%3}, {%4,%5,%6,%7}, {%8,%9}, {%0,%1,%2,%3};\n"
        : "+f"(d[0]), "+f"(d[1]), "+f"(d[2]), "+f"(d[3])
        : "r"(a[0]), "r"(a[1]), "r"(a[2]), "r"(a[3]), "r"(b[0]), "r"(b[1]));
}
#define CP_COMMIT()  asm volatile("cp.async.commit_group;" ::: "memory")
#define CP_WAIT0()   asm volatile("cp.async.wait_group 0;" ::: "memory")

// ---------------- CSR build (by src) ----------------
__global__ void zero_cnt() {
    int i = blockIdx.x * blockDim.x + threadIdx.x;
    if (i < N_SRC) g_cnt[i] = 0;
}
__global__ void hist_kernel(const int* __restrict__ src) {
    int e = blockIdx.x * blockDim.x + threadIdx.x;   // exact 800000
    atomicAdd(&g_cnt[src[e]], 1);
}
__global__ void __launch_bounds__(1024)
scan_kernel() {
    __shared__ int sh[1024];
    const int t = threadIdx.x;
    const int CH = 49;                 // 49*1024 >= 50000
    int base = t * CH;
    int sum = 0;
    for (int i = 0; i < CH; i++) {
        int idx = base + i;
        if (idx < N_SRC) sum += g_cnt[idx];
    }
    sh[t] = sum;
    __syncthreads();
    for (int off = 1; off < 1024; off <<= 1) {
        int v = (t >= off) ? sh[t - off] : 0;
        __syncthreads();
        sh[t] += v;
        __syncthreads();
    }
    int run = sh[t] - sum;
    for (int i = 0; i < CH; i++) {
        int idx = base + i;
        if (idx < N_SRC) {
            g_rowp[idx] = run;
            g_cur[idx] = run;
            run += g_cnt[idx];
        }
    }
    if (t == 0) g_rowp[N_SRC] = E_NUM;
}
__global__ void scatter_kernel(const int* __restrict__ src) {
    int e = blockIdx.x * blockDim.x + threadIdx.x;   // exact 800000
    int pos = atomicAdd(&g_cur[src[e]], 1);
    g_eid[pos] = e;
}

// ---------------- init: zero out, s=0 ----------------
__global__ void init_kernel(float* __restrict__ out) {
    int i = blockIdx.x * blockDim.x + threadIdx.x;   // exact 3,200,000
    out[i] = 0.f;
    if (i < N_DST * NHEAD) g_s[i] = 0.f;
}

// ---------------- prep: wsum, bias concat ----------------
__global__ void prep_misc(const float* __restrict__ W_fij,
                          const float* __restrict__ b_ns) {
    int t = threadIdx.x;   // 320 threads
    if (t < HE) {
        float s = 0.f;
#pragma unroll
        for (int k = 0; k < 16; k++) s += W_fij[k * HE + t];
        g_wsum[t] = s;
    }
    g_bcat[t] = (t < HN) ? b_ns[t] : 0.f;
}

// ---------------- prep: scaled weight concat + scaled W_nj copy ------------
__global__ void prep_wcat(const float* __restrict__ W_ns,
                          const float* __restrict__ W_ni,
                          const float* __restrict__ W_nj) {
    int i = blockIdx.x * blockDim.x + threadIdx.x;   // exact 40960
    int k = i / NCAT, n = i % NCAT;
    g_wcat[i] = CFAC * ((n < HN) ? W_ns[k * HN + n] : W_ni[k * HE + (n - HN)]);
    if (i < IN_NODE * HE) g_wnj[i] = CFAC * W_nj[i];
}

// ---------------- tf32 tensor-core GEMM, cp.async pipelined ----------------
#define GBM 128
#define GBN 64
#define GBK 32
#define ASTR 36
#define BSTR 72
#define A_WORDS (GBM*ASTR)
#define B_WORDS (GBK*BSTR)
#define GEMM_SMEM ((2*A_WORDS + 2*B_WORDS) * 4)   // 55296 B

__global__ void __launch_bounds__(256)
gemm_all(const float* __restrict__ nfeats, const float* __restrict__ dstf)
{
    const float *A, *B, *bias;
    float *C;
    int N, n0;
    if (blockIdx.y < 5) {
        A = nfeats; B = g_wcat; bias = g_bcat; C = g_proj;
        N = NCAT; n0 = blockIdx.y * GBN;
    } else {
        A = dstf; B = g_wnj; bias = nullptr; C = g_fnj;
        N = HE; n0 = 0;
    }
    const int M  = N_SRC;
    const int m0 = blockIdx.x * GBM;

    extern __shared__ uint32_t sm[];
    uint32_t* AsB[2] = { sm, sm + A_WORDS };
    uint32_t* BsB[2] = { sm + 2*A_WORDS, sm + 2*A_WORDS + B_WORDS };
    const uint32_t sbase = (uint32_t)__cvta_generic_to_shared(sm);

    const int tid  = threadIdx.x;
    const int w    = tid >> 5;
    const int lane = tid & 31;
    const int g4   = lane >> 2;
    const int k4   = lane & 3;
    const int mw   = w & 3;
    const int nw   = w >> 2;

    const int ar0 = tid >> 3, ac = tid & 7;
    const int br0 = tid >> 4, bn4 = tid & 15;

    float4 bv[2];

    float acc[2][4][4];
#pragma unroll
    for (int t = 0; t < 2; t++)
#pragma unroll
        for (int nt = 0; nt < 4; nt++)
#pragma unroll
            for (int j = 0; j < 4; j++) acc[t][nt][j] = 0.f;

    auto aasync = [&](int k0, int buf) {
        uint32_t dbase = sbase + (uint32_t)(buf * A_WORDS) * 4;
#pragma unroll
        for (int i = 0; i < 4; i++) {
            int row = ar0 + 32 * i;
            int gm  = m0 + row;
            const float* gp = A + (size_t)gm * IN_NODE + k0 + ac * 4;
            uint32_t daddr = dbase + (uint32_t)(row * ASTR + ac * 4) * 4;
            uint32_t ssz = (gm < M) ? 16u : 0u;
            asm volatile("cp.async.cg.shared.global [%0], [%1], 16, %2;"
                         :: "r"(daddr), "l"(gp), "r"(ssz) : "memory");
        }
    };
    auto bload = [&](int k0) {
        bv[0] = __ldg((const float4*)(B + (size_t)(k0 + br0) * N + n0 + bn4 * 4));
        bv[1] = __ldg((const float4*)(B + (size_t)(k0 + br0 + 16) * N + n0 + bn4 * 4));
    };
    auto bstore = [&](int buf) {
#pragma unroll
        for (int i = 0; i < 2; i++) {
            uint32_t* p = &BsB[buf][(br0 + 16 * i) * BSTR + bn4 * 4];
            p[0] = f2tf(bv[i].x); p[1] = f2tf(bv[i].y);
            p[2] = f2tf(bv[i].z); p[3] = f2tf(bv[i].w);
        }
    };
    auto compute = [&](int buf) {
        const uint32_t* Asb = AsB[buf];
        const uint32_t* Bsb = BsB[buf];
#pragma unroll
        for (int kt = 0; kt < 4; kt++) {
            uint32_t afr[2][4], bfr[4][2];
            const int kb = kt * 8;
#pragma unroll
            for (int t = 0; t < 2; t++) {
                int rbase = (mw * 32 + t * 16 + g4) * ASTR + kb + k4;
                afr[t][0] = Asb[rbase];
                afr[t][1] = Asb[rbase + 8 * ASTR];
                afr[t][2] = Asb[rbase + 4];
                afr[t][3] = Asb[rbase + 8 * ASTR + 4];
            }
#pragma unroll
            for (int nt = 0; nt < 4; nt++) {
                int n = nw * 32 + nt * 8 + g4;
                bfr[nt][0] = Bsb[(kb + k4) * BSTR + n];
                bfr[nt][1] = Bsb[(kb + k4 + 4) * BSTR + n];
            }
#pragma unroll
            for (int t = 0; t < 2; t++)
#pragma unroll
                for (int nt = 0; nt < 4; nt++)
                    mma_tf32(acc[t][nt], afr[t], bfr[nt]);
        }
    };

    aasync(0, 0); CP_COMMIT();
    bload(0);
    bstore(0);
    CP_WAIT0();
    __syncthreads();

#pragma unroll
    for (int kk = 0; kk < IN_NODE / GBK; kk++) {
        int buf = kk & 1;
        if (kk < IN_NODE / GBK - 1) {
            aasync((kk + 1) * GBK, buf ^ 1); CP_COMMIT();
            bload((kk + 1) * GBK);
        }
        compute(buf);
        if (kk < IN_NODE / GBK - 1) {
            bstore(buf ^ 1);
            CP_WAIT0();
            __syncthreads();
        }
    }

#pragma unroll
    for (int t = 0; t < 2; t++) {
        int r0 = m0 + mw * 32 + t * 16 + g4;
#pragma unroll
        for (int nt = 0; nt < 4; nt++) {
            int col = n0 + nw * 32 + nt * 8 + 2 * k4;
            float b0 = 0.f, b1 = 0.f;
            if (bias) { b0 = bias[col]; b1 = bias[col + 1]; }
            if (r0 < M)
                *(float2*)(C + (size_t)r0 * N + col) =
                    make_float2(acc[t][nt][0] + b0, acc[t][nt][1] + b1);
            if (r0 + 8 < M)
                *(float2*)(C + (size_t)(r0 + 8) * N + col) =
                    make_float2(acc[t][nt][2] + b0, acc[t][nt][3] + b1);
        }
    }
}

// ---------------- fused edge attention: logit -> exp -> segment sum --------
// 16 threads per edge (R5-proven config).
__global__ void __launch_bounds__(256)
edge_attn(const int* __restrict__ src, const int* __restrict__ dst,
          const float* __restrict__ reward,
          const float* __restrict__ attn, const float* __restrict__ b_e)
{
    int gi   = blockIdx.x * blockDim.x + threadIdx.x;
    int e    = gi >> 4;
    int lane = gi & 15;
    int w    = threadIdx.x & 31;

    int si = src[e];
    int d  = dst[e];
    float r = reward[e];

    float4 f  = *(const float4*)(g_proj + (size_t)si * NCAT + HN + lane * 4);
    float4 nj = *(const float4*)(g_fnj + (size_t)d * HE + lane * 4);
    float4 ws = ((const float4*)g_wsum)[lane];
    float4 be = ((const float4*)b_e)[lane];

    f.x = leaky(f.x + nj.x + r * ws.x + be.x);
    f.y = leaky(f.y + nj.y + r * ws.y + be.y);
    f.z = leaky(f.z + nj.z + r * ws.z + be.z);
    f.w = leaky(f.w + nj.w + r * ws.w + be.w);

    float4 at = ((const float4*)attn)[lane];
    float p = f.x * at.x + f.y * at.y + f.z * at.z + f.w * at.w;
    p += __shfl_xor_sync(0xffffffffu, p, 1);
    p += __shfl_xor_sync(0xffffffffu, p, 2);
    float ph = __shfl_sync(0xffffffffu, p, (w & 16) + ((w & 3) << 2));

    if (lane < 4) {
        float a = __expf(ph);
        g_a[(size_t)e * NHEAD + lane] = a;
        redAddF1(g_s + (size_t)d * NHEAD + lane, a);
    }
}

// ---------------- inv_s: g_is = 0.25 / s (head-mean folded) ----------------
__global__ void inv_s_kernel() {
    int i = blockIdx.x * blockDim.x + threadIdx.x;
    if (i < N_DST * NHEAD) {
        float s = g_s[i];
        g_is[i] = 0.25f / (s > 0.f ? s : 1.f);
    }
}

// ---------------- src-CSR aggregation: 16 lanes per src --------------------
// h_src row loaded ONCE per src; per edge only broadcast loads + red.v4.
__global__ void __launch_bounds__(256)
edge_agg_src(const int* __restrict__ dst, float* __restrict__ out)
{
    int gi   = blockIdx.x * blockDim.x + threadIdx.x;
    int s    = gi >> 4;                  // src id; grid exact 50000*16
    int lane = gi & 15;

    int beg = g_rowp[s];
    int end = g_rowp[s + 1];
    if (beg == end) return;

    const float4* hp = (const float4*)(g_proj + (size_t)s * NCAT) + lane;
    float4 v0 = hp[0];
    float4 v1 = hp[16];
    float4 v2 = hp[32];
    float4 v3 = hp[48];

    for (int pos = beg; pos < end; pos++) {
        int eid = g_eid[pos];
        int d   = __ldg(dst + eid);
        float4 av  = *(const float4*)(g_a + (size_t)eid * NHEAD);   // bcast
        float4 isv = *(const float4*)(g_is + (size_t)d * NHEAD);    // bcast
        float c0 = av.x * isv.x;
        float c1 = av.y * isv.y;
        float c2 = av.z * isv.z;
        float c3 = av.w * isv.w;

        float4 acc;
        acc.x = c0 * v0.x + c1 * v1.x + c2 * v2.x + c3 * v3.x;
        acc.y = c0 * v0.y + c1 * v1.y + c2 * v2.y + c3 * v3.y;
        acc.z = c0 * v0.z + c1 * v1.z + c2 * v2.z + c3 * v3.z;
        acc.w = c0 * v0.w + c1 * v1.w + c2 * v2.w + c3 * v3.w;

        redAddF4((float4*)out + (size_t)d * 16 + lane, acc);
    }
}

// ---------------- finalize: relu only (0.25 folded into g_is) --------------
__global__ void __launch_bounds__(256)
finalize(float* __restrict__ out)
{
    int i = blockIdx.x * blockDim.x + threadIdx.x;   // exact 3,200,000
    out[i] = fmaxf(out[i], 0.f);
}

// ---------------- launch ----------------
extern "C" void kernel_launch(void* const* d_in, const int* in_sizes, int n_in,
                              void* d_out, int out_size)
{
    const float* nfeats  = (const float*)d_in[0];
    const float* dstf    = (const float*)d_in[1];
    const float* reward  = (const float*)d_in[2];
    const int*   src     = (const int*)  d_in[3];
    const int*   dst     = (const int*)  d_in[4];
    const float* W_ns    = (const float*)d_in[5];
    const float* b_ns    = (const float*)d_in[6];
    const float* W_ni    = (const float*)d_in[7];
    const float* W_nj    = (const float*)d_in[8];
    const float* W_fij   = (const float*)d_in[9];
    const float* attn    = (const float*)d_in[10];
    const float* b_e     = (const float*)d_in[11];
    float* out = (float*)d_out;

    cudaFuncSetAttribute(gemm_all, cudaFuncAttributeMaxDynamicSharedMemorySize,
                         GEMM_SMEM);

    // CSR build (independent of GEMM inputs)
    zero_cnt<<<(N_SRC + 255) / 256, 256>>>();
    hist_kernel<<<E_NUM / 256, 256>>>(src);
    scan_kernel<<<1, 1024>>>();
    scatter_kernel<<<E_NUM / 256, 256>>>(src);

    init_kernel<<<OUT_ELEMS / 256, 256>>>(out);
    prep_misc<<<1, NCAT>>>(W_fij, b_ns);
    prep_wcat<<<IN_NODE * NCAT / 256, 256>>>(W_ns, W_ni, W_nj);

    dim3 gg((N_SRC + GBM - 1) / GBM, 6);
    gemm_all<<<gg, 256, GEMM_SMEM>>>(nfeats, dstf);

    edge_attn<<<E_NUM * 16 / 256, 256>>>(src, dst, reward, attn, b_e);
    inv_s_kernel<<<(N_DST * NHEAD + 255) / 256, 256>>>();
    edge_agg_src<<<N_SRC * 16 / 256, 256>>>(dst, out);
    finalize<<<OUT_ELEMS / 256, 256>>>(out);
}

// round 13
// speedup vs baseline: 1.0609x; 1.0609x over previous
#include <cuda_runtime.h>
#include <math.h>
#include <stdint.h>

// ---------------- problem constants ----------------
#define N_SRC   50000
#define N_DST   50000
#define E_NUM   800000
#define IN_NODE 128
#define OUT_NODE 64
#define NHEAD   4
#define HN      (NHEAD*OUT_NODE)   // 256
#define HE      64                 // NHEAD*OUT_EDGE
#define NCAT    (HN + HE)          // 320
#define SLOPE   0.01f
#define OUT_ELEMS (N_DST*OUT_NODE) // 3,200,000
// compensation for tf32-truncation of A (mean rel bias -2^-11*ln2)
#define CFAC    1.000338f

// ---------------- scratch (device globals; allocation-free) ----------------
__device__ __align__(16) float g_proj[(size_t)N_SRC * NCAT];   // 64 MB
__device__ __align__(16) float g_fnj [(size_t)N_DST * HE];     // 12.8 MB
__device__ __align__(16) float g_a   [(size_t)E_NUM * NHEAD];
__device__ __align__(16) float g_s   [(size_t)N_DST * NHEAD];
__device__ __align__(16) float g_is  [(size_t)N_DST * NHEAD];  // 0.25/s
__device__ __align__(16) float g_wcat[IN_NODE * NCAT];
__device__ __align__(16) float g_wnj [IN_NODE * HE];
__device__ __align__(16) float g_bcat[NCAT];
__device__ __align__(16) float g_wsum[HE];

// ---------------- helpers ----------------
__device__ __forceinline__ void redAddF4(float4* p, float4 v) {
    asm volatile("red.global.add.v4.f32 [%0], {%1, %2, %3, %4};"
                 :: "l"(__cvta_generic_to_global(p)),
                    "f"(v.x), "f"(v.y), "f"(v.z), "f"(v.w)
                 : "memory");
}
__device__ __forceinline__ void redAddF1(float* p, float v) {
    asm volatile("red.global.add.f32 [%0], %1;"
                 :: "l"(__cvta_generic_to_global(p)), "f"(v) : "memory");
}
__device__ __forceinline__ float leaky(float x) {
    return x >= 0.f ? x : SLOPE * x;
}
__device__ __forceinline__ uint32_t f2tf(float f) {
    uint32_t r;
    asm("cvt.rna.tf32.f32 %0, %1;" : "=r"(r) : "f"(f));
    return r;
}
__device__ __forceinline__ void mma_tf32(float* d, const uint32_t* a, const uint32_t* b) {
    asm volatile(
        "mma.sync.aligned.m16n8k8.row.col.f32.tf32.tf32.f32 "
        "{%0,%1,%2,%3}, {%4,%5,%6,%7}, {%8,%9}, {%0,%1,%2,%3};\n"
        : "+f"(d[0]), "+f"(d[1]), "+f"(d[2]), "+f"(d[3])
        : "r"(a[0]), "r"(a[1]), "r"(a[2]), "r"(a[3]), "r"(b[0]), "r"(b[1]));
}
#define CP_COMMIT()  asm volatile("cp.async.commit_group;" ::: "memory")
#define CP_WAIT0()   asm volatile("cp.async.wait_group 0;" ::: "memory")

// ---------------- init: zero out, s=0 ----------------
__global__ void init_kernel(float* __restrict__ out) {
    int i = blockIdx.x * blockDim.x + threadIdx.x;   // exact 3,200,000
    out[i] = 0.f;
    if (i < N_DST * NHEAD) g_s[i] = 0.f;
}

// ---------------- prep: wsum, bias concat ----------------
__global__ void prep_misc(const float* __restrict__ W_fij,
                          const float* __restrict__ b_ns) {
    int t = threadIdx.x;   // 320 threads
    if (t < HE) {
        float s = 0.f;
#pragma unroll
        for (int k = 0; k < 16; k++) s += W_fij[k * HE + t];
        g_wsum[t] = s;
    }
    g_bcat[t] = (t < HN) ? b_ns[t] : 0.f;
}

// ---------------- prep: scaled weight concat + scaled W_nj copy ------------
__global__ void prep_wcat(const float* __restrict__ W_ns,
                          const float* __restrict__ W_ni,
                          const float* __restrict__ W_nj) {
    int i = blockIdx.x * blockDim.x + threadIdx.x;   // exact 40960
    int k = i / NCAT, n = i % NCAT;
    g_wcat[i] = CFAC * ((n < HN) ? W_ns[k * HN + n] : W_ni[k * HE + (n - HN)]);
    if (i < IN_NODE * HE) g_wnj[i] = CFAC * W_nj[i];
}

// ---------------- tf32 tensor-core GEMM, cp.async pipelined (R6, 50.8us) ---
#define GBM 128
#define GBN 64
#define GBK 32
#define ASTR 36
#define BSTR 72
#define A_WORDS (GBM*ASTR)
#define B_WORDS (GBK*BSTR)
#define GEMM_SMEM ((2*A_WORDS + 2*B_WORDS) * 4)   // 55296 B

__global__ void __launch_bounds__(256)
gemm_all(const float* __restrict__ nfeats, const float* __restrict__ dstf)
{
    const float *A, *B, *bias;
    float *C;
    int N, n0;
    if (blockIdx.y < 5) {
        A = nfeats; B = g_wcat; bias = g_bcat; C = g_proj;
        N = NCAT; n0 = blockIdx.y * GBN;
    } else {
        A = dstf; B = g_wnj; bias = nullptr; C = g_fnj;
        N = HE; n0 = 0;
    }
    const int M  = N_SRC;
    const int m0 = blockIdx.x * GBM;

    extern __shared__ uint32_t sm[];
    uint32_t* AsB[2] = { sm, sm + A_WORDS };
    uint32_t* BsB[2] = { sm + 2*A_WORDS, sm + 2*A_WORDS + B_WORDS };
    const uint32_t sbase = (uint32_t)__cvta_generic_to_shared(sm);

    const int tid  = threadIdx.x;
    const int w    = tid >> 5;
    const int lane = tid & 31;
    const int g4   = lane >> 2;
    const int k4   = lane & 3;
    const int mw   = w & 3;
    const int nw   = w >> 2;

    const int ar0 = tid >> 3, ac = tid & 7;
    const int br0 = tid >> 4, bn4 = tid & 15;

    float4 bv[2];

    float acc[2][4][4];
#pragma unroll
    for (int t = 0; t < 2; t++)
#pragma unroll
        for (int nt = 0; nt < 4; nt++)
#pragma unroll
            for (int j = 0; j < 4; j++) acc[t][nt][j] = 0.f;

    auto aasync = [&](int k0, int buf) {
        uint32_t dbase = sbase + (uint32_t)(buf * A_WORDS) * 4;
#pragma unroll
        for (int i = 0; i < 4; i++) {
            int row = ar0 + 32 * i;
            int gm  = m0 + row;
            const float* gp = A + (size_t)gm * IN_NODE + k0 + ac * 4;
            uint32_t daddr = dbase + (uint32_t)(row * ASTR + ac * 4) * 4;
            uint32_t ssz = (gm < M) ? 16u : 0u;
            asm volatile("cp.async.cg.shared.global [%0], [%1], 16, %2;"
                         :: "r"(daddr), "l"(gp), "r"(ssz) : "memory");
        }
    };
    auto bload = [&](int k0) {
        bv[0] = __ldg((const float4*)(B + (size_t)(k0 + br0) * N + n0 + bn4 * 4));
        bv[1] = __ldg((const float4*)(B + (size_t)(k0 + br0 + 16) * N + n0 + bn4 * 4));
    };
    auto bstore = [&](int buf) {
#pragma unroll
        for (int i = 0; i < 2; i++) {
            uint32_t* p = &BsB[buf][(br0 + 16 * i) * BSTR + bn4 * 4];
            p[0] = f2tf(bv[i].x); p[1] = f2tf(bv[i].y);
            p[2] = f2tf(bv[i].z); p[3] = f2tf(bv[i].w);
        }
    };
    auto compute = [&](int buf) {
        const uint32_t* Asb = AsB[buf];
        const uint32_t* Bsb = BsB[buf];
#pragma unroll
        for (int kt = 0; kt < 4; kt++) {
            uint32_t afr[2][4], bfr[4][2];
            const int kb = kt * 8;
#pragma unroll
            for (int t = 0; t < 2; t++) {
                int rbase = (mw * 32 + t * 16 + g4) * ASTR + kb + k4;
                afr[t][0] = Asb[rbase];
                afr[t][1] = Asb[rbase + 8 * ASTR];
                afr[t][2] = Asb[rbase + 4];
                afr[t][3] = Asb[rbase + 8 * ASTR + 4];
            }
#pragma unroll
            for (int nt = 0; nt < 4; nt++) {
                int n = nw * 32 + nt * 8 + g4;
                bfr[nt][0] = Bsb[(kb + k4) * BSTR + n];
                bfr[nt][1] = Bsb[(kb + k4 + 4) * BSTR + n];
            }
#pragma unroll
            for (int t = 0; t < 2; t++)
#pragma unroll
                for (int nt = 0; nt < 4; nt++)
                    mma_tf32(acc[t][nt], afr[t], bfr[nt]);
        }
    };

    aasync(0, 0); CP_COMMIT();
    bload(0);
    bstore(0);
    CP_WAIT0();
    __syncthreads();

#pragma unroll
    for (int kk = 0; kk < IN_NODE / GBK; kk++) {
        int buf = kk & 1;
        if (kk < IN_NODE / GBK - 1) {
            aasync((kk + 1) * GBK, buf ^ 1); CP_COMMIT();
            bload((kk + 1) * GBK);
        }
        compute(buf);
        if (kk < IN_NODE / GBK - 1) {
            bstore(buf ^ 1);
            CP_WAIT0();
            __syncthreads();
        }
    }

#pragma unroll
    for (int t = 0; t < 2; t++) {
        int r0 = m0 + mw * 32 + t * 16 + g4;
#pragma unroll
        for (int nt = 0; nt < 4; nt++) {
            int col = n0 + nw * 32 + nt * 8 + 2 * k4;
            float b0 = 0.f, b1 = 0.f;
            if (bias) { b0 = bias[col]; b1 = bias[col + 1]; }
            if (r0 < M)
                *(float2*)(C + (size_t)r0 * N + col) =
                    make_float2(acc[t][nt][0] + b0, acc[t][nt][1] + b1);
            if (r0 + 8 < M)
                *(float2*)(C + (size_t)(r0 + 8) * N + col) =
                    make_float2(acc[t][nt][2] + b0, acc[t][nt][3] + b1);
        }
    }
}

// ---------------- fused edge attention (R5-proven, plain loads) ------------
__global__ void __launch_bounds__(256)
edge_attn(const int* __restrict__ src, const int* __restrict__ dst,
          const float* __restrict__ reward,
          const float* __restrict__ attn, const float* __restrict__ b_e)
{
    int gi   = blockIdx.x * blockDim.x + threadIdx.x;
    int e    = gi >> 4;
    int lane = gi & 15;
    int w    = threadIdx.x & 31;

    int si = src[e];
    int d  = dst[e];
    float r = reward[e];

    float4 f  = *(const float4*)(g_proj + (size_t)si * NCAT + HN + lane * 4);
    float4 nj = *(const float4*)(g_fnj + (size_t)d * HE + lane * 4);
    float4 ws = ((const float4*)g_wsum)[lane];
    float4 be = ((const float4*)b_e)[lane];

    f.x = leaky(f.x + nj.x + r * ws.x + be.x);
    f.y = leaky(f.y + nj.y + r * ws.y + be.y);
    f.z = leaky(f.z + nj.z + r * ws.z + be.z);
    f.w = leaky(f.w + nj.w + r * ws.w + be.w);

    float4 at = ((const float4*)attn)[lane];
    float p = f.x * at.x + f.y * at.y + f.z * at.z + f.w * at.w;
    p += __shfl_xor_sync(0xffffffffu, p, 1);
    p += __shfl_xor_sync(0xffffffffu, p, 2);
    float ph = __shfl_sync(0xffffffffu, p, (w & 16) + ((w & 3) << 2));

    if (lane < 4) {
        float a = __expf(ph);
        g_a[(size_t)e * NHEAD + lane] = a;
        redAddF1(g_s + (size_t)d * NHEAD + lane, a);
    }
}

// ---------------- inv_s: g_is = 0.25 / s (head-mean folded) ----------------
__global__ void inv_s_kernel() {
    int i = blockIdx.x * blockDim.x + threadIdx.x;
    if (i < N_DST * NHEAD) {
        float s = g_s[i];
        g_is[i] = 0.25f / (s > 0.f ? s : 1.f);
    }
}

// ---------------- head-combined weighted aggregation (R5 structure) --------
__global__ void __launch_bounds__(256)
edge_agg(const int* __restrict__ src, const int* __restrict__ dst,
         float* __restrict__ out)
{
    int gi   = blockIdx.x * blockDim.x + threadIdx.x;
    int e    = gi >> 4;
    int lane = gi & 15;

    int si = src[e];
    int d  = dst[e];

    float4 avv = *(const float4*)(g_a + (size_t)e * NHEAD);
    float4 isv = *(const float4*)(g_is + (size_t)d * NHEAD);
    float a0 = avv.x * isv.x;
    float a1 = avv.y * isv.y;
    float a2 = avv.z * isv.z;
    float a3 = avv.w * isv.w;

    const float4* hp = (const float4*)(g_proj + (size_t)si * NCAT);
    float4 v0 = hp[lane];
    float4 v1 = hp[16 + lane];
    float4 v2 = hp[32 + lane];
    float4 v3 = hp[48 + lane];

    float4 acc;
    acc.x = a0 * v0.x + a1 * v1.x + a2 * v2.x + a3 * v3.x;
    acc.y = a0 * v0.y + a1 * v1.y + a2 * v2.y + a3 * v3.y;
    acc.z = a0 * v0.z + a1 * v1.z + a2 * v2.z + a3 * v3.z;
    acc.w = a0 * v0.w + a1 * v1.w + a2 * v2.w + a3 * v3.w;

    redAddF4((float4*)out + (size_t)d * 16 + lane, acc);
}

// ---------------- finalize: relu only (0.25 folded into g_is) --------------
__global__ void __launch_bounds__(256)
finalize(float* __restrict__ out)
{
    int i = blockIdx.x * blockDim.x + threadIdx.x;   // exact 3,200,000
    out[i] = fmaxf(out[i], 0.f);
}

// ---------------- launch ----------------
extern "C" void kernel_launch(void* const* d_in, const int* in_sizes, int n_in,
                              void* d_out, int out_size)
{
    const float* nfeats  = (const float*)d_in[0];
    const float* dstf    = (const float*)d_in[1];
    const float* reward  = (const float*)d_in[2];
    const int*   src     = (const int*)  d_in[3];
    const int*   dst     = (const int*)  d_in[4];
    const float* W_ns    = (const float*)d_in[5];
    const float* b_ns    = (const float*)d_in[6];
    const float* W_ni    = (const float*)d_in[7];
    const float* W_nj    = (const float*)d_in[8];
    const float* W_fij   = (const float*)d_in[9];
    const float* attn    = (const float*)d_in[10];
    const float* b_e     = (const float*)d_in[11];
    float* out = (float*)d_out;

    cudaFuncSetAttribute(gemm_all, cudaFuncAttributeMaxDynamicSharedMemorySize,
                         GEMM_SMEM);

    init_kernel<<<OUT_ELEMS / 256, 256>>>(out);
    prep_misc<<<1, NCAT>>>(W_fij, b_ns);
    prep_wcat<<<IN_NODE * NCAT / 256, 256>>>(W_ns, W_ni, W_nj);

    dim3 gg((N_SRC + GBM - 1) / GBM, 6);   // 391 x 6: all three projections
    gemm_all<<<gg, 256, GEMM_SMEM>>>(nfeats, dstf);

    edge_attn<<<E_NUM * 16 / 256, 256>>>(src, dst, reward, attn, b_e);
    inv_s_kernel<<<(N_DST * NHEAD + 255) / 256, 256>>>();
    edge_agg <<<E_NUM * 16 / 256, 256>>>(src, dst, out);
    finalize <<<OUT_ELEMS / 256, 256>>>(out);
}

// round 14
// speedup vs baseline: 1.4730x; 1.3885x over previous
#include <cuda_runtime.h>
#include <math.h>
#include <stdint.h>

// ---------------- problem constants ----------------
#define N_SRC   50000
#define N_DST   50000
#define E_NUM   800000
#define IN_NODE 128
#define OUT_NODE 64
#define NHEAD   4
#define HN      (NHEAD*OUT_NODE)   // 256
#define HE      64                 // NHEAD*OUT_EDGE
#define NCAT    (HN + HE)          // 320
#define SLOPE   0.01f
#define OUT_ELEMS (N_DST*OUT_NODE) // 3,200,000
// compensation for tf32-truncation of BOTH A and B (each -2^-11*ln2 mean bias)
#define CFAC2   1.000676f

// ---------------- scratch (device globals; allocation-free) ----------------
__device__ __align__(16) float g_proj[(size_t)N_SRC * NCAT];   // 64 MB
__device__ __align__(16) float g_fnj [(size_t)N_DST * HE];     // 12.8 MB
__device__ __align__(16) float g_a   [(size_t)E_NUM * NHEAD];
__device__ __align__(16) float g_s   [(size_t)N_DST * NHEAD];
__device__ __align__(16) float g_is  [(size_t)N_DST * NHEAD];  // 0.25/s
__device__ __align__(16) float g_wcat[IN_NODE * NCAT];
__device__ __align__(16) float g_wnj [IN_NODE * HE];
__device__ __align__(16) float g_bcat[NCAT];
__device__ __align__(16) float g_wsum[HE];

// ---------------- helpers ----------------
__device__ __forceinline__ void redAddF4(float4* p, float4 v) {
    asm volatile("red.global.add.v4.f32 [%0], {%1, %2, %3, %4};"
                 :: "l"(__cvta_generic_to_global(p)),
                    "f"(v.x), "f"(v.y), "f"(v.z), "f"(v.w)
                 : "memory");
}
__device__ __forceinline__ float leaky(float x) {
    return x >= 0.f ? x : SLOPE * x;
}
__device__ __forceinline__ void mma_tf32(float* d, const uint32_t* a, const uint32_t* b) {
    asm volatile(
        "mma.sync.aligned.m16n8k8.row.col.f32.tf32.tf32.f32 "
        "{%0,%1,%2,%3}, {%4,%5,%6,%7}, {%8,%9}, {%0,%1,%2,%3};\n"
        : "+f"(d[0]), "+f"(d[1]), "+f"(d[2]), "+f"(d[3])
        : "r"(a[0]), "r"(a[1]), "r"(a[2]), "r"(a[3]), "r"(b[0]), "r"(b[1]));
}
#define CP_COMMIT()  asm volatile("cp.async.commit_group;" ::: "memory")
#define CP_WAIT0()   asm volatile("cp.async.wait_group 0;" ::: "memory")

// ---------------- init: zero out, s=0 ----------------
__global__ void init_kernel(float* __restrict__ out) {
    int i = blockIdx.x * blockDim.x + threadIdx.x;   // exact 3,200,000
    out[i] = 0.f;
    if (i < N_DST * NHEAD) g_s[i] = 0.f;
}

// ---------------- prep: wsum, bias concat ----------------
__global__ void prep_misc(const float* __restrict__ W_fij,
                          const float* __restrict__ b_ns) {
    int t = threadIdx.x;   // 320 threads
    if (t < HE) {
        float s = 0.f;
#pragma unroll
        for (int k = 0; k < 16; k++) s += W_fij[k * HE + t];
        g_wsum[t] = s;
    }
    g_bcat[t] = (t < HN) ? b_ns[t] : 0.f;
}

// ---------------- prep: CFAC2-scaled weight concat + W_nj copy -------------
__global__ void prep_wcat(const float* __restrict__ W_ns,
                          const float* __restrict__ W_ni,
                          const float* __restrict__ W_nj) {
    int i = blockIdx.x * blockDim.x + threadIdx.x;   // exact 40960
    int k = i / NCAT, n = i % NCAT;
    g_wcat[i] = CFAC2 * ((n < HN) ? W_ns[k * HN + n] : W_ni[k * HE + (n - HN)]);
    if (i < IN_NODE * HE) g_wnj[i] = CFAC2 * W_nj[i];
}

// ---------------- tf32 tensor-core GEMM, full cp.async pipeline ------------
// grid = (391, 6).  y<5: g_proj = nfeats @ [W_ns|W_ni] + [b_ns|0]  (N=320)
//                   y==5: g_fnj = dst_feats @ W_nj                  (N=64)
// Both A and B land in smem as raw fp32 bits; HW MMA truncates to tf32.
// Mean truncation bias compensated by CFAC2 pre-scale on weights.
#define GBM 128
#define GBN 64
#define GBK 32
#define ASTR 36
#define BSTR 72
#define A_WORDS (GBM*ASTR)
#define B_WORDS (GBK*BSTR)
#define GEMM_SMEM ((2*A_WORDS + 2*B_WORDS) * 4)   // 55296 B

__global__ void __launch_bounds__(256)
gemm_all(const float* __restrict__ nfeats, const float* __restrict__ dstf)
{
    const float *A, *B, *bias;
    float *C;
    int N, n0;
    if (blockIdx.y < 5) {
        A = nfeats; B = g_wcat; bias = g_bcat; C = g_proj;
        N = NCAT; n0 = blockIdx.y * GBN;
    } else {
        A = dstf; B = g_wnj; bias = nullptr; C = g_fnj;
        N = HE; n0 = 0;
    }
    const int M  = N_SRC;
    const int m0 = blockIdx.x * GBM;

    extern __shared__ uint32_t sm[];
    uint32_t* AsB[2] = { sm, sm + A_WORDS };
    uint32_t* BsB[2] = { sm + 2*A_WORDS, sm + 2*A_WORDS + B_WORDS };
    const uint32_t sbase = (uint32_t)__cvta_generic_to_shared(sm);

    const int tid  = threadIdx.x;
    const int w    = tid >> 5;
    const int lane = tid & 31;
    const int g4   = lane >> 2;
    const int k4   = lane & 3;
    const int mw   = w & 3;
    const int nw   = w >> 2;

    const int ar0 = tid >> 3, ac = tid & 7;
    const int br0 = tid >> 4, bn4 = tid & 15;

    float acc[2][4][4];
#pragma unroll
    for (int t = 0; t < 2; t++)
#pragma unroll
        for (int nt = 0; nt < 4; nt++)
#pragma unroll
            for (int j = 0; j < 4; j++) acc[t][nt][j] = 0.f;

    // A tile (128x32) + B tile (32x64) both via cp.async, one group per stage
    auto absync = [&](int k0, int buf) {
        uint32_t dA = sbase + (uint32_t)(buf * A_WORDS) * 4;
#pragma unroll
        for (int i = 0; i < 4; i++) {
            int row = ar0 + 32 * i;
            int gm  = m0 + row;
            const float* gp = A + (size_t)gm * IN_NODE + k0 + ac * 4;
            uint32_t daddr = dA + (uint32_t)(row * ASTR + ac * 4) * 4;
            uint32_t ssz = (gm < M) ? 16u : 0u;
            asm volatile("cp.async.cg.shared.global [%0], [%1], 16, %2;"
                         :: "r"(daddr), "l"(gp), "r"(ssz) : "memory");
        }
        uint32_t dB = sbase + (uint32_t)((2 * A_WORDS) + buf * B_WORDS) * 4;
#pragma unroll
        for (int i = 0; i < 2; i++) {
            int k = br0 + 16 * i;
            const float* gp = B + (size_t)(k0 + k) * N + n0 + bn4 * 4;
            uint32_t daddr = dB + (uint32_t)(k * BSTR + bn4 * 4) * 4;
            asm volatile("cp.async.cg.shared.global [%0], [%1], 16;"
                         :: "r"(daddr), "l"(gp) : "memory");
        }
    };
    auto compute = [&](int buf) {
        const uint32_t* Asb = AsB[buf];
        const uint32_t* Bsb = BsB[buf];
#pragma unroll
        for (int kt = 0; kt < 4; kt++) {
            uint32_t afr[2][4], bfr[4][2];
            const int kb = kt * 8;
#pragma unroll
            for (int t = 0; t < 2; t++) {
                int rbase = (mw * 32 + t * 16 + g4) * ASTR + kb + k4;
                afr[t][0] = Asb[rbase];
                afr[t][1] = Asb[rbase + 8 * ASTR];
                afr[t][2] = Asb[rbase + 4];
                afr[t][3] = Asb[rbase + 8 * ASTR + 4];
            }
#pragma unroll
            for (int nt = 0; nt < 4; nt++) {
                int n = nw * 32 + nt * 8 + g4;
                bfr[nt][0] = Bsb[(kb + k4) * BSTR + n];
                bfr[nt][1] = Bsb[(kb + k4 + 4) * BSTR + n];
            }
#pragma unroll
            for (int t = 0; t < 2; t++)
#pragma unroll
                for (int nt = 0; nt < 4; nt++)
                    mma_tf32(acc[t][nt], afr[t], bfr[nt]);
        }
    };

    absync(0, 0); CP_COMMIT();
    CP_WAIT0();
    __syncthreads();

#pragma unroll
    for (int kk = 0; kk < IN_NODE / GBK; kk++) {
        int buf = kk & 1;
        if (kk < IN_NODE / GBK - 1) {
            absync((kk + 1) * GBK, buf ^ 1); CP_COMMIT();
        }
        compute(buf);
        if (kk < IN_NODE / GBK - 1) {
            CP_WAIT0();
            __syncthreads();
        }
    }

    // epilogue: c0,c1 -> (row, col..col+1); c2,c3 -> (row+8, ...)
#pragma unroll
    for (int t = 0; t < 2; t++) {
        int r0 = m0 + mw * 32 + t * 16 + g4;
#pragma unroll
        for (int nt = 0; nt < 4; nt++) {
            int col = n0 + nw * 32 + nt * 8 + 2 * k4;
            float b0 = 0.f, b1 = 0.f;
            if (bias) { b0 = bias[col]; b1 = bias[col + 1]; }
            if (r0 < M)
                *(float2*)(C + (size_t)r0 * N + col) =
                    make_float2(acc[t][nt][0] + b0, acc[t][nt][1] + b1);
            if (r0 + 8 < M)
                *(float2*)(C + (size_t)(r0 + 8) * N + col) =
                    make_float2(acc[t][nt][2] + b0, acc[t][nt][3] + b1);
        }
    }
}

// ---------------- fused edge attention: logit -> exp -> segment sum --------
// 16 threads per edge; lane 0 of each 16-group does ONE st.v4 + ONE red.v4.
__global__ void __launch_bounds__(256)
edge_attn(const int* __restrict__ src, const int* __restrict__ dst,
          const float* __restrict__ reward,
          const float* __restrict__ attn, const float* __restrict__ b_e)
{
    int gi   = blockIdx.x * blockDim.x + threadIdx.x;
    int e    = gi >> 4;
    int lane = gi & 15;
    int w    = threadIdx.x & 31;

    int si = src[e];
    int d  = dst[e];
    float r = reward[e];

    float4 f  = *(const float4*)(g_proj + (size_t)si * NCAT + HN + lane * 4);
    float4 nj = *(const float4*)(g_fnj + (size_t)d * HE + lane * 4);
    float4 ws = ((const float4*)g_wsum)[lane];
    float4 be = ((const float4*)b_e)[lane];

    f.x = leaky(f.x + nj.x + r * ws.x + be.x);
    f.y = leaky(f.y + nj.y + r * ws.y + be.y);
    f.z = leaky(f.z + nj.z + r * ws.z + be.z);
    f.w = leaky(f.w + nj.w + r * ws.w + be.w);

    float4 at = ((const float4*)attn)[lane];
    float p = f.x * at.x + f.y * at.y + f.z * at.z + f.w * at.w;
    p += __shfl_xor_sync(0xffffffffu, p, 1);
    p += __shfl_xor_sync(0xffffffffu, p, 2);
    // lane L of each 16-group fetches head (L&3) logit; lanes 0-3 -> heads 0-3
    float ph = __shfl_sync(0xffffffffu, p, (w & 16) + ((w & 3) << 2));
    float a  = __expf(ph);
    // gather heads 1..3 into lane 0 / lane 16
    float a1 = __shfl_sync(0xffffffffu, a, (w & 16) + 1);
    float a2 = __shfl_sync(0xffffffffu, a, (w & 16) + 2);
    float a3 = __shfl_sync(0xffffffffu, a, (w & 16) + 3);

    if (lane == 0) {
        float4 av = make_float4(a, a1, a2, a3);
        *(float4*)(g_a + (size_t)e * NHEAD) = av;
        redAddF4((float4*)g_s + d, av);
    }
}

// ---------------- inv_s: g_is = 0.25 / s (head-mean folded) ----------------
__global__ void inv_s_kernel() {
    int i = blockIdx.x * blockDim.x + threadIdx.x;
    if (i < N_DST * NHEAD) {
        float s = g_s[i];
        g_is[i] = 0.25f / (s > 0.f ? s : 1.f);
    }
}

// ---------------- head-combined weighted aggregation -----------------------
__global__ void __launch_bounds__(256)
edge_agg(const int* __restrict__ src, const int* __restrict__ dst,
         float* __restrict__ out)
{
    int gi   = blockIdx.x * blockDim.x + threadIdx.x;
    int e    = gi >> 4;
    int lane = gi & 15;

    int si = src[e];
    int d  = dst[e];

    float4 avv = *(const float4*)(g_a + (size_t)e * NHEAD);
    float4 isv = *(const float4*)(g_is + (size_t)d * NHEAD);
    float a0 = avv.x * isv.x;
    float a1 = avv.y * isv.y;
    float a2 = avv.z * isv.z;
    float a3 = avv.w * isv.w;

    const float4* hp = (const float4*)(g_proj + (size_t)si * NCAT);
    float4 v0 = hp[lane];
    float4 v1 = hp[16 + lane];
    float4 v2 = hp[32 + lane];
    float4 v3 = hp[48 + lane];

    float4 acc;
    acc.x = a0 * v0.x + a1 * v1.x + a2 * v2.x + a3 * v3.x;
    acc.y = a0 * v0.y + a1 * v1.y + a2 * v2.y + a3 * v3.y;
    acc.z = a0 * v0.z + a1 * v1.z + a2 * v2.z + a3 * v3.z;
    acc.w = a0 * v0.w + a1 * v1.w + a2 * v2.w + a3 * v3.w;

    redAddF4((float4*)out + (size_t)d * 16 + lane, acc);
}

// ---------------- finalize: relu only (0.25 folded into g_is) --------------
__global__ void __launch_bounds__(256)
finalize(float* __restrict__ out)
{
    int i = blockIdx.x * blockDim.x + threadIdx.x;   // exact 3,200,000
    out[i] = fmaxf(out[i], 0.f);
}

// ---------------- launch ----------------
extern "C" void kernel_launch(void* const* d_in, const int* in_sizes, int n_in,
                              void* d_out, int out_size)
{
    const float* nfeats  = (const float*)d_in[0];
    const float* dstf    = (const float*)d_in[1];
    const float* reward  = (const float*)d_in[2];
    const int*   src     = (const int*)  d_in[3];
    const int*   dst     = (const int*)  d_in[4];
    const float* W_ns    = (const float*)d_in[5];
    const float* b_ns    = (const float*)d_in[6];
    const float* W_ni    = (const float*)d_in[7];
    const float* W_nj    = (const float*)d_in[8];
    const float* W_fij   = (const float*)d_in[9];
    const float* attn    = (const float*)d_in[10];
    const float* b_e     = (const float*)d_in[11];
    float* out = (float*)d_out;

    cudaFuncSetAttribute(gemm_all, cudaFuncAttributeMaxDynamicSharedMemorySize,
                         GEMM_SMEM);

    init_kernel<<<OUT_ELEMS / 256, 256>>>(out);
    prep_misc<<<1, NCAT>>>(W_fij, b_ns);
    prep_wcat<<<IN_NODE * NCAT / 256, 256>>>(W_ns, W_ni, W_nj);

    dim3 gg((N_SRC + GBM - 1) / GBM, 6);   // 391 x 6: all three projections
    gemm_all<<<gg, 256, GEMM_SMEM>>>(nfeats, dstf);

    edge_attn<<<E_NUM * 16 / 256, 256>>>(src, dst, reward, attn, b_e);
    inv_s_kernel<<<(N_DST * NHEAD + 255) / 256, 256>>>();
    edge_agg <<<E_NUM * 16 / 256, 256>>>(src, dst, out);
    finalize <<<OUT_ELEMS / 256, 256>>>(out);
}